// round 15
// baseline (speedup 1.0000x reference)
#include <cuda_runtime.h>
#include <cuda_bf16.h>
#include <cstdint>

#define Bc   32
#define Tc   400
#define Jc   30
#define Hc   150
#define H2c  300
#define H3c  450
#define TP1c 401
#define K8c  19                  // ceil(152/8) k-chunks of 8 (k padded to 152)
#define PACKB_ELEMS (K8c*H3c*8)  // 68400 bf16 per packed gru weight
#define MRc  608                 // match combined rows: 450 Whh + 150 WrT + 8 pad
#define PACKM_ELEMS (K8c*MRc*8)  // 92416 bf16 per packed match weight

typedef unsigned long long ull;

// ---------------- device scratch ----------------
__device__ float g_gictx[Bc*Tc*H3c];
__device__ float g_giq  [Bc*Jc*H3c];
__device__ float g_Hp   [Bc*Tc*Hc];
__device__ float g_Hq   [Bc*Jc*Hc];
__device__ float g_whq  [Bc*Jc*Hc];
__device__ float g_preWp[Bc*Tc*Hc];
__device__ float g_gixf [Bc*Tc*H3c];
__device__ float g_gixb [Bc*Tc*H3c];
__device__ float g_qpf  [Bc*Jc*H3c];
__device__ float g_qpb  [Bc*Jc*H3c];
__device__ float g_Hr   [Bc*TP1c*H2c];
__device__ float g_enc  [Bc*TP1c*H2c];
__device__ __align__(16) __nv_bfloat16 g_packsb[2*PACKB_ELEMS];
__device__ __align__(16) __nv_bfloat16 g_packm [2*PACKM_ELEMS];

// ---------------- fast activations ----------------
__device__ __forceinline__ float fast_ex2(float x){ float y; asm("ex2.approx.f32 %0, %1;" : "=f"(y) : "f"(x)); return y; }
__device__ __forceinline__ float tanh_f(float x){ float y; asm("tanh.approx.f32 %0, %1;" : "=f"(y) : "f"(x)); return y; }
__device__ __forceinline__ float sigm(float x){ return fmaf(tanh_f(0.5f*x), 0.5f, 0.5f); }

// ---------------- f32x2 packed math ----------------
__device__ __forceinline__ void ffma2(ull &acc, ull a, ull b){
  asm("fma.rn.f32x2 %0, %1, %2, %0;" : "+l"(acc) : "l"(a), "l"(b));
}
__device__ __forceinline__ ull packf2(float x){
  ull r; asm("mov.b64 %0, {%1, %1};" : "=l"(r) : "f"(x)); return r;
}
__device__ __forceinline__ ull pack2(float x, float y){
  ull r; asm("mov.b64 %0, {%1, %2};" : "=l"(r) : "f"(x), "f"(y)); return r;
}
__device__ __forceinline__ float2 unpackf2(ull v){
  float lo, hi; asm("mov.b64 {%0, %1}, %2;" : "=f"(lo), "=f"(hi) : "l"(v));
  return make_float2(lo, hi);
}
// EXACT bf16x2 -> f32x2: bf16 is truncated fp32 (lo: <<16, hi: mask)
__device__ __forceinline__ ull bf2f2(uint32_t w){
  uint32_t lo = w << 16;
  uint32_t hi = w & 0xFFFF0000u;
  ull r; asm("mov.b64 %0, {%1, %2};" : "=l"(r) : "r"(lo), "r"(hi)); return r;
}
// 8 MACs: w = 8 bf16 (k..k+7), h0/h1 = matching fp32 values; two f32x2 accumulators
__device__ __forceinline__ void fma8v2(uint4 w, float4 h0, float4 h1, ull &accA, ull &accB){
  ffma2(accA, bf2f2(w.x), pack2(h0.x, h0.y));
  ffma2(accB, bf2f2(w.y), pack2(h0.z, h0.w));
  ffma2(accA, bf2f2(w.z), pack2(h1.x, h1.y));
  ffma2(accB, bf2f2(w.w), pack2(h1.z, h1.w));
}
__device__ __forceinline__ float finish2(ull accA, ull accB, float init){
  float2 a = unpackf2(accA), b = unpackf2(accB);
  return init + ((a.x + a.y) + (b.x + b.y));
}
__device__ __forceinline__ float4 ld4(const float* p){ return *reinterpret_cast<const float4*>(p); }

// ---------------- cluster / mbarrier / cp.async helpers ----------------
__device__ __forceinline__ uint32_t smem_u32(const void* p){
  uint32_t a; asm("{ .reg .u64 t; cvta.to.shared.u64 t, %1; cvt.u32.u64 %0, t; }" : "=r"(a) : "l"(p));
  return a;
}
__device__ __forceinline__ uint32_t mapa_u32(uint32_t a, uint32_t rank){
  uint32_t r; asm("mapa.shared::cluster.u32 %0, %1, %2;" : "=r"(r) : "r"(a), "r"(rank));
  return r;
}
__device__ __forceinline__ void mbar_init(uint32_t a, uint32_t cnt){
  asm volatile("mbarrier.init.shared.b64 [%0], %1;" :: "r"(a), "r"(cnt) : "memory");
}
__device__ __forceinline__ void mbar_arrive_cluster(uint32_t remote){
  asm volatile("mbarrier.arrive.release.cluster.shared::cluster.b64 _, [%0];" :: "r"(remote) : "memory");
}
__device__ __forceinline__ void mbar_wait(uint32_t a, uint32_t parity){
  uint32_t done;
  asm volatile("{\n\t.reg .pred p;\n\t"
    "mbarrier.try_wait.parity.acquire.cluster.shared::cta.b64 p, [%1], %2;\n\t"
    "selp.b32 %0, 1, 0, p;\n\t}" : "=r"(done) : "r"(a), "r"(parity) : "memory");
  while (!done) {
    asm volatile("{\n\t.reg .pred p;\n\t"
      "mbarrier.try_wait.parity.acquire.cluster.shared::cta.b64 p, [%1], %2, 0x989680;\n\t"
      "selp.b32 %0, 1, 0, p;\n\t}" : "=r"(done) : "r"(a), "r"(parity) : "memory");
  }
}
__device__ __forceinline__ void sts_remote_f32(uint32_t a, float v){
  asm volatile("st.shared::cluster.f32 [%0], %1;" :: "r"(a), "f"(v) : "memory");
}
__device__ __forceinline__ void cp_async4(uint32_t saddr, const void* gptr, bool ok){
  int sz = ok ? 4 : 0;
  asm volatile("cp.async.ca.shared.global [%0], [%1], 4, %2;"
               :: "r"(saddr), "l"(gptr), "r"(sz) : "memory");
}
#define CP_COMMIT() asm volatile("cp.async.commit_group;" ::: "memory")
#define CLUSTER_SYNC_() do{ \
  asm volatile("barrier.cluster.arrive.aligned;" ::: "memory"); \
  asm volatile("barrier.cluster.wait.aligned;" ::: "memory"); } while(0)

// ---------------- shared GEMM body: cp.async 3-stage pipelined, FFMA2 compute ----------------
__device__ __forceinline__ void gemm_body(
    const float* __restrict__ A, const int* __restrict__ idx,
    const float* __restrict__ W, const float* __restrict__ bias,
    float* __restrict__ C, int M, int N, int K, int lda, int ldw,
    bool transw, bool gather)
{
  __shared__ __align__(16) float As[3][16][132];
  __shared__ __align__(16) float Bs[3][16][68];
  __shared__ int sidx[128];
  int m0 = blockIdx.y*128, n0 = blockIdx.x*64;
  int tid = threadIdx.x;
  int tx = tid & 15, ty = tid >> 4;
  ull acc2[8][2] = {};
  int nk = (K + 15) >> 4;

  if (gather) {
    for (int i = tid; i < 128; i += 256) {
      int gm = m0 + i;
      sidx[i] = (gm < M) ? idx[gm] : 0;
    }
    __syncthreads();
  }
  uint32_t asb = smem_u32(&As[0][0][0]);
  uint32_t bsb = smem_u32(&Bs[0][0][0]);

  auto issue_tile = [&](int itile){
    int bo = itile % 3;
    int k0 = itile*16;
    uint32_t abase = asb + (uint32_t)bo*16*132*4;
    uint32_t bbase = bsb + (uint32_t)bo*16*68*4;
    #pragma unroll
    for (int it = 0; it < 8; it++) {
      int li = tid + it*256;
      int m = li >> 4, k = li & 15;
      int gm = m0 + m, gk = k0 + k;
      bool ok = (gm < M) && (gk < K);
      int row = gather ? sidx[m] : gm;
      const float* src = A + (size_t)(ok ? row : 0)*lda + (ok ? gk : 0);
      cp_async4(abase + (uint32_t)(k*132 + m)*4, src, ok);
    }
    #pragma unroll
    for (int it = 0; it < 4; it++) {
      int li = tid + it*256;
      if (transw) {
        int n = li >> 4, k = li & 15;
        int gn = n0 + n, gk = k0 + k;
        bool ok = (gn < N) && (gk < K);
        const float* src = W + (size_t)(ok ? gn : 0)*ldw + (ok ? gk : 0);
        cp_async4(bbase + (uint32_t)(k*68 + n)*4, src, ok);
      } else {
        int k = li >> 6, n = li & 63;
        int gn = n0 + n, gk = k0 + k;
        bool ok = (gn < N) && (gk < K);
        const float* src = W + (size_t)(ok ? gk : 0)*ldw + (ok ? gn : 0);
        cp_async4(bbase + (uint32_t)(k*68 + n)*4, src, ok);
      }
    }
    CP_COMMIT();
  };

  issue_tile(0);
  if (nk > 1) issue_tile(1);
  for (int itile = 0; itile < nk; itile++) {
    if (itile + 2 < nk) {
      issue_tile(itile + 2);
      asm volatile("cp.async.wait_group 2;" ::: "memory");
    } else if (itile + 1 < nk) {
      asm volatile("cp.async.wait_group 1;" ::: "memory");
    } else {
      asm volatile("cp.async.wait_group 0;" ::: "memory");
    }
    __syncthreads();
    int cb = itile % 3;
    #pragma unroll
    for (int k = 0; k < 16; k++) {
      const ull* bv2 = reinterpret_cast<const ull*>(&Bs[cb][k][tx*4]);
      ull b01 = bv2[0], b23 = bv2[1];
      float4 a0 = *reinterpret_cast<const float4*>(&As[cb][k][ty*8]);
      float4 a1 = *reinterpret_cast<const float4*>(&As[cb][k][ty*8+4]);
      float am[8] = {a0.x,a0.y,a0.z,a0.w,a1.x,a1.y,a1.z,a1.w};
      #pragma unroll
      for (int i = 0; i < 8; i++) {
        ull am2 = packf2(am[i]);
        ffma2(acc2[i][0], am2, b01);
        ffma2(acc2[i][1], am2, b23);
      }
    }
    __syncthreads();
  }

  #pragma unroll
  for (int i = 0; i < 8; i++) {
    int gm = m0 + ty*8 + i;
    if (gm >= M) continue;
    float2 p0 = unpackf2(acc2[i][0]);
    float2 p1 = unpackf2(acc2[i][1]);
    float vals[4] = {p0.x, p0.y, p1.x, p1.y};
    #pragma unroll
    for (int j = 0; j < 4; j++) {
      int gn = n0 + tx*4 + j;
      if (gn < N) {
        float v = vals[j];
        if (bias) v += bias[gn];
        C[(size_t)gm*N + gn] = v;
      }
    }
  }
}

template<bool TRANSW, bool GATHER>
__global__ void __launch_bounds__(256) gemm_kernel(
    const float* __restrict__ A, const int* __restrict__ idx,
    const float* __restrict__ W, const float* __restrict__ bias,
    float* __restrict__ C, int M, int N, int K, int lda, int ldw)
{
  gemm_body(A, idx, W, bias, C, M, N, K, lda, ldw, TRANSW, GATHER);
}

struct GDesc {
  const float* A; const int* idx; const float* W; const float* bias; float* C;
  int M, N, K, lda, ldw, transw, gather, gx, gy;
};
struct G6 { GDesc d[6]; };

__global__ void __launch_bounds__(256) multigemm6_kernel(G6 g)
{
  GDesc d = g.d[blockIdx.z];
  if ((int)blockIdx.x >= d.gx || (int)blockIdx.y >= d.gy) return;
  gemm_body(d.A, d.idx, d.W, d.bias, d.C, d.M, d.N, d.K, d.lda, d.ldw,
            d.transw != 0, d.gather != 0);
}

// ---------------- prep: z0/z1 = embedding GEMMs, z2..5 = weight packs ----------------
__global__ void __launch_bounds__(256) prep_kernel(
    GDesc d0, GDesc d1,
    const float* __restrict__ ctx_Whh, const float* __restrict__ q_Whh,
    const float* __restrict__ m_Whh,  const float* __restrict__ mr_Whh,
    const float* __restrict__ Wr,
    __nv_bfloat16* __restrict__ P_ctx, __nv_bfloat16* __restrict__ P_q,
    __nv_bfloat16* __restrict__ Pm_f,  __nv_bfloat16* __restrict__ Pm_b)
{
  int z = blockIdx.z;
  if (z < 2) {
    GDesc d = z ? d1 : d0;
    if ((int)blockIdx.x >= d.gx || (int)blockIdx.y >= d.gy) return;
    gemm_body(d.A, d.idx, d.W, d.bias, d.C, d.M, d.N, d.K, d.lda, d.ldw,
              d.transw != 0, d.gather != 0);
    return;
  }
  int i = (blockIdx.y*8 + blockIdx.x)*256 + threadIdx.x;
  if (z < 4) {
    if (i >= PACKB_ELEMS) return;
    const float* W = (z == 3) ? q_Whh : ctx_Whh;
    __nv_bfloat16* out = (z == 3) ? P_q : P_ctx;
    int kk = i & 7, rest = i >> 3;
    int n = rest % H3c, k8 = rest / H3c, k = k8*8 + kk;
    out[i] = __float2bfloat16((k < Hc) ? W[n*Hc + k] : 0.f);
  } else {
    if (i >= PACKM_ELEMS) return;
    const float* Whh = (z == 4) ? m_Whh : mr_Whh;
    __nv_bfloat16* out = (z == 4) ? Pm_f : Pm_b;
    int kk = i & 7, rest = i >> 3;
    int row = rest % MRc, k8 = rest / MRc, k = k8*8 + kk;
    float v = 0.f;
    if (k < Hc) {
      if (row < H3c)      v = Whh[row*Hc + k];
      else if (row < 600) v = Wr[k*Hc + (row - H3c)];
    }
    out[i] = __float2bfloat16(v);
  }
}

// ---------------- GRU scans: single CTA per chain, shift-trick FFMA2 inner loop ----------------
#define GRU_SMEM (K8c*H3c*16)   // 136800 B

__global__ void __launch_bounds__(480,1) gru_scan_kernel(
    const float* __restrict__ gictx, const float* __restrict__ giq,
    const uint4* __restrict__ PctxWhh, const uint4* __restrict__ PqWhh,
    const float* __restrict__ ctx_bhh, const float* __restrict__ q_bhh,
    float* __restrict__ Hp, float* __restrict__ Hq)
{
  extern __shared__ uint4 sW4g[];  // [k8*450 + n]
  __shared__ float sh[152];
  __shared__ float sgh[452];
  int tid = threadIdx.x;
  int isq = blockIdx.x >> 5;
  int b   = blockIdx.x & 31;
  const float* gi   = isq ? (giq + (size_t)b*Jc*H3c) : (gictx + (size_t)b*Tc*H3c);
  const uint4* Wsrc = isq ? PqWhh : PctxWhh;
  const float* bhh  = isq ? q_bhh : ctx_bhh;
  float*       outp = isq ? (Hq + (size_t)b*Jc*Hc) : (Hp + (size_t)b*Tc*Hc);
  int Tlen = isq ? Jc : Tc;

  for (int i = tid; i < K8c*H3c; i += 480) sW4g[i] = Wsrc[i];
  float my_b = (tid < H3c) ? bhh[tid] : 0.f;
  if (tid < 152) sh[tid] = 0.f;
  __syncthreads();

  for (int t = 0; t < Tlen; t++) {
    float gi0=0.f, gi1=0.f, gi2=0.f;
    if (tid < Hc) {
      const float* gr = gi + (size_t)t*H3c;
      gi0 = gr[tid]; gi1 = gr[Hc+tid]; gi2 = gr[2*Hc+tid];
    }
    if (tid < H3c) {
      ull accA = 0ull, accB = 0ull;
      const uint4* wr = sW4g + tid;
      #pragma unroll
      for (int k8 = 0; k8 < K8c; k8++) {
        uint4 w = wr[k8*H3c];
        fma8v2(w, ld4(sh + k8*8), ld4(sh + k8*8 + 4), accA, accB);
      }
      sgh[tid] = finish2(accA, accB, my_b);
    }
    __syncthreads();
    if (tid < Hc) {
      float r  = sigm(gi0 + sgh[tid]);
      float z  = sigm(gi1 + sgh[Hc + tid]);
      float nn = tanh_f(gi2 + r*sgh[2*Hc + tid]);
      float hn = nn + z*(sh[tid] - nn);
      sh[tid] = hn;
      outp[(size_t)t*Hc + tid] = hn;
    }
    __syncthreads();
  }
}

// ---------------- match scans: k-split attention, 2-CTA cluster, ONE exchange/step ----------------
// rank0: gh rows 0..299 + e rows 450..524 (e[0:75))   -> 375 rows, attention k-half [0,75)
// rank1: gh rows 300..449 + e rows 525..599 (e[75:150)) -> 225 rows, attention k-half [75,150)
// Exchange per step: my gh rows + my 30 partial attention scores (single mbar arrive/wait).
#define MATCH_THREADS 512
#define R0_ROWS 375
#define R1_ROWS 225
#define MATCH_WSMEM (K8c*R0_ROWS*16)                       // 114000 B (max of both ranks)
#define MATCH_DSMEM (MATCH_WSMEM + 450*32*2 + Jc*152*2)    // +28800+9120 = 151920 B

__global__ void __launch_bounds__(MATCH_THREADS,1) __cluster_dims__(2,1,1)
match_kernel(
    const float* __restrict__ whq,  const float* __restrict__ preWp,
    const float* __restrict__ gixf, const float* __restrict__ gixb,
    const float* __restrict__ qpf,  const float* __restrict__ qpb,
    const float* __restrict__ wvec,
    const uint4* __restrict__ WcPf, const uint4* __restrict__ WcPb,
    const float* __restrict__ m_bhh, const float* __restrict__ mr_bhh,
    float* __restrict__ Hr)
{
  extern __shared__ uint4 sWm[];                            // [19][R] my rows
  __nv_bfloat16* sQPT = (__nv_bfloat16*)((char*)sWm + MATCH_WSMEM); // [450][32]
  __nv_bfloat16* sWhq = sQPT + 450*32;                      // [30][152]
  __shared__ float sh [152];
  __shared__ float sw [152];
  __shared__ float se [152];          // e rows (my half only)
  __shared__ float sS [32];           // raw partial attention scores (local)
  __shared__ float sghe[2][456];      // double-buffered full gh (450)
  __shared__ float sPS [2][64];       // double-buffered partial scores [buf][rank*32+j]
  __shared__ __align__(8) unsigned long long mbar_in;

  int tid = threadIdx.x;
  uint32_t rank; asm("mov.u32 %0, %%cluster_ctarank;" : "=r"(rank));
  int chain = blockIdx.x >> 1;      // 0..63
  int dir = chain >> 5;
  int b   = chain & 31;

  const float* gix = (dir ? gixb : gixf) + (size_t)b*Tc*H3c;
  const float* qp  = (dir ? qpb  : qpf)  + (size_t)b*Jc*H3c;
  const uint4* Wc  = dir ? WcPb : WcPf;
  const float* bhh = dir ? mr_bhh : m_bhh;
  const float* preW = preWp + (size_t)b*Tc*Hc;

  int R = rank ? R1_ROWS : R0_ROWS;          // my row count
  int khb = rank ? 75 : 0;                   // my attention k-half base

  // local row -> global combined row
  // rank0: l<300 -> l          ; l>=300 -> 450 + (l-300)      (e[0..74])
  // rank1: l<150 -> 300 + l    ; l>=150 -> 525 + (l-150)      (e[75..149])
  auto l2g = [&](int l)->int{
    if (rank == 0) return (l < 300) ? l : (450 + (l - 300));
    else           return (l < 150) ? (300 + l) : (525 + (l - 150));
  };

  // preamble: weights (my rows), qproj^T, whq
  for (int i = tid; i < K8c*R; i += MATCH_THREADS) {
    int k8 = i / R, rl = i % R;
    sWm[i] = Wc[k8*MRc + l2g(rl)];
  }
  for (int i = tid; i < Jc*H3c; i += MATCH_THREADS) {
    int j = i / H3c, n = i % H3c;
    sQPT[n*32 + j] = __float2bfloat16(qp[i]);
  }
  for (int n = tid; n < H3c; n += MATCH_THREADS) {
    sQPT[n*32 + 30] = __float2bfloat16(0.f);
    sQPT[n*32 + 31] = __float2bfloat16(0.f);
  }
  for (int i = tid; i < Jc*Hc; i += MATCH_THREADS) {
    int j = i / Hc, k = i % Hc;
    sWhq[j*152 + k] = __float2bfloat16(whq[(size_t)b*Jc*Hc + i]);
  }
  if (tid < 152) { sw[tid] = (tid < Hc) ? wvec[tid] : 0.f; sh[tid] = 0.f; }
  if (rank == 0 && tid < Hc) Hr[((size_t)b*TP1c)*H2c + dir*Hc + tid] = 0.f;
  int grow = (tid < R) ? l2g(tid) : 0;       // my global row index
  bool is_e = (tid < R) && (grow >= H3c);
  float my_bhh = (tid < R && !is_e) ? bhh[grow] : 0.f;
  if (tid == 0) mbar_init(smem_u32(&mbar_in), 1);
  __syncthreads();
  CLUSTER_SYNC_();
  uint32_t peer_sghe = mapa_u32(smem_u32(&sghe[0][0]), rank ^ 1);
  uint32_t peer_sPS  = mapa_u32(smem_u32(&sPS[0][0]),  rank ^ 1);
  uint32_t peer_mbar = mapa_u32(smem_u32(&mbar_in), rank ^ 1);
  uint32_t my_mbar   = smem_u32(&mbar_in);

  for (int step = 0; step < Tc; step++) {
    int t = dir ? (Tc-1-step) : step;
    int buf = step & 1;

    // prefetch per-step gate inputs (consumed in S4) + preW for my e-rows
    float g0=0.f, g1=0.f, g2=0.f;
    if (tid < Hc) {
      const float* gr = gix + (size_t)t*H3c;
      g0 = gr[tid]; g1 = gr[Hc+tid]; g2 = gr[2*Hc+tid];
    }
    float pw = 0.f;
    if (is_e) pw = preW[(size_t)t*Hc + (grow - H3c)];

    // S1: my rows of the combined matvec
    if (tid < R) {
      float init = is_e ? pw : my_bhh;
      ull accA = 0ull, accB = 0ull;
      #pragma unroll
      for (int k8 = 0; k8 < K8c; k8++) {
        uint4 w = sWm[k8*R + tid];
        fma8v2(w, ld4(sh + k8*8), ld4(sh + k8*8 + 4), accA, accB);
      }
      float acc = finish2(accA, accB, init);
      if (!is_e) {
        sghe[buf][grow] = acc;
        sts_remote_f32(peer_sghe + (uint32_t)(buf*456 + grow)*4u, acc);
      } else {
        se[grow - H3c] = acc;      // my e half, local only
      }
    }
    __syncthreads();

    // S2: partial attention scores over my k-half (all 30 j, 16 warps x 2 j)
    {
      int wid = tid >> 5, lane = tid & 31;
      #pragma unroll
      for (int jj = 0; jj < 2; jj++) {
        int j = wid*2 + jj;
        if (j < Jc) {
          float p = 0.f;
          for (int k = khb + lane; k < khb + 75; k += 32)
            p = fmaf(tanh_f(__bfloat162float(sWhq[j*152 + k]) + se[k]), sw[k], p);
          #pragma unroll
          for (int o = 16; o; o >>= 1) p += __shfl_xor_sync(0xffffffffu, p, o);
          if (lane == 0) sS[j] = p;
        }
      }
    }
    __syncthreads();

    // send my 30 partial scores (local + remote), then arrive + wait (ONE exchange)
    if (tid < Jc) {
      float p = sS[tid];
      int slot = (int)rank*32 + tid;
      sPS[buf][slot] = p;
      sts_remote_f32(peer_sPS + (uint32_t)(buf*64 + slot)*4u, p);
    }
    __syncthreads();
    if (tid == 0) mbar_arrive_cluster(peer_mbar);
    mbar_wait(my_mbar, (uint32_t)buf);

    // S3: softmax over J=30 from the two partials (warp 0, replicated both ranks)
    if (tid < 32) {
      float v = (tid < Jc) ? (sPS[buf][tid] + sPS[buf][32 + tid]) : -1e30f;
      float m = v;
      #pragma unroll
      for (int o = 16; o; o >>= 1) m = fmaxf(m, __shfl_xor_sync(0xffffffffu, m, o));
      float e = (tid < Jc) ? fast_ex2(1.442695041f*(v - m)) : 0.f;
      float su = e;
      #pragma unroll
      for (int o = 16; o; o >>= 1) su += __shfl_xor_sync(0xffffffffu, su, o);
      sS[tid] = e * __fdividef(1.f, su);
    }
    __syncthreads();

    // S4: gates + GRU update (replicated, bitwise identical); Hr store on rank0
    if (tid < Hc) {
      ull aR = 0ull, bR = 0ull, aZ = 0ull, bZ = 0ull, aN = 0ull, bN = 0ull;
      const uint4* qr = reinterpret_cast<const uint4*>(sQPT + tid*32);
      const uint4* qz = reinterpret_cast<const uint4*>(sQPT + (Hc + tid)*32);
      const uint4* qn = reinterpret_cast<const uint4*>(sQPT + (2*Hc + tid)*32);
      #pragma unroll
      for (int jj = 0; jj < 4; jj++) {
        float4 a0 = ld4(&sS[jj*8]);
        float4 a1 = ld4(&sS[jj*8 + 4]);
        fma8v2(qr[jj], a0, a1, aR, bR);
        fma8v2(qz[jj], a0, a1, aZ, bZ);
        fma8v2(qn[jj], a0, a1, aN, bN);
      }
      float gr_ = finish2(aR, bR, g0);
      float gz_ = finish2(aZ, bZ, g1);
      float gn_ = finish2(aN, bN, g2);
      float r  = sigm(gr_ + sghe[buf][tid]);
      float z  = sigm(gz_ + sghe[buf][Hc+tid]);
      float nn = tanh_f(gn_ + r*sghe[buf][2*Hc+tid]);
      float hn = nn + z*(sh[tid] - nn);
      sh[tid] = hn;
      if (rank == 0) Hr[((size_t)b*TP1c + 1 + step)*H2c + dir*Hc + tid] = hn;
    }
    __syncthreads();
  }
  CLUSTER_SYNC_();
}

// ---------------- pointer decoder (32 blocks, 2 steps) ----------------
__global__ void __launch_bounds__(512,1) ptr_kernel(
    const float* __restrict__ Hr, const float* __restrict__ enc,
    const float* __restrict__ ptr_W2, const float* __restrict__ ptr_v,
    const float* __restrict__ d_Wih, const float* __restrict__ d_Whh,
    const float* __restrict__ d_bih, const float* __restrict__ d_bhh,
    float* __restrict__ out)
{
  __shared__ float sh[H2c], shw[H2c], sc[H2c], sa[TP1c + 3], sgi[900], sgh[900];
  __shared__ float red[2];
  int b = blockIdx.x, tid = threadIdx.x;
  int wid = tid >> 5, lane = tid & 31;
  const float* encb = enc + (size_t)b*TP1c*H2c;
  const float* Hrb  = Hr  + (size_t)b*TP1c*H2c;
  if (tid < H2c) sh[tid] = 0.f;
  __syncthreads();

  for (int step = 0; step < 2; step++) {
    if (tid < H2c) {
      float a = 0.f;
      for (int j = 0; j < H2c; j++) a = fmaf(sh[j], ptr_W2[(size_t)j*H2c + tid], a);
      shw[tid] = a;
    }
    __syncthreads();
    for (int t = wid; t < TP1c; t += 16) {
      float p = 0.f;
      const float* er = encb + (size_t)t*H2c;
      for (int k = lane; k < H2c; k += 32) p = fmaf(tanh_f(er[k] + shw[k]), ptr_v[k], p);
      #pragma unroll
      for (int o = 16; o; o >>= 1) p += __shfl_xor_sync(0xffffffffu, p, o);
      if (lane == 0) sa[t] = p;
    }
    __syncthreads();
    if (tid < 32) {
      float m = -1e30f;
      for (int t = lane; t < TP1c; t += 32) m = fmaxf(m, sa[t]);
      #pragma unroll
      for (int o = 16; o; o >>= 1) m = fmaxf(m, __shfl_xor_sync(0xffffffffu, m, o));
      if (lane == 0) red[0] = m;
    }
    __syncthreads();
    float mm = red[0];
    for (int t = tid; t < TP1c; t += 512) sa[t] = fast_ex2(1.442695041f*(sa[t] - mm));
    __syncthreads();
    if (tid < 32) {
      float s = 0.f;
      for (int t = lane; t < TP1c; t += 32) s += sa[t];
      #pragma unroll
      for (int o = 16; o; o >>= 1) s += __shfl_xor_sync(0xffffffffu, s, o);
      if (lane == 0) red[1] = __fdividef(1.f, s);
    }
    __syncthreads();
    float inv = red[1];
    for (int t = tid; t < TP1c; t += 512) {
      float a = sa[t] * inv;
      sa[t] = a;
      out[((size_t)b*2 + step)*TP1c + t] = a;
    }
    __syncthreads();
    if (tid < H2c) {
      float a = 0.f;
      for (int t = 0; t < TP1c; t++) a = fmaf(sa[t], Hrb[(size_t)t*H2c + tid], a);
      sc[tid] = a;
    }
    __syncthreads();
    for (int n = tid; n < 900; n += 512) {
      float gi = d_bih[n], gh = d_bhh[n];
      const float* wi = d_Wih + (size_t)n*H2c;
      const float* wh = d_Whh + (size_t)n*H2c;
      for (int k = 0; k < H2c; k++) { gi = fmaf(sc[k], wi[k], gi); gh = fmaf(sh[k], wh[k], gh); }
      sgi[n] = gi; sgh[n] = gh;
    }
    __syncthreads();
    if (tid < H2c) {
      float r  = sigm(sgi[tid] + sgh[tid]);
      float z  = sigm(sgi[H2c+tid] + sgh[H2c+tid]);
      float nn = tanh_f(sgi[2*H2c+tid] + r*sgh[2*H2c+tid]);
      sh[tid] = nn + z*(sh[tid] - nn);
    }
    __syncthreads();
  }
}

// ---------------- host ----------------
static void* sym(const void* s) { void* p = nullptr; cudaGetSymbolAddress(&p, s); return p; }

extern "C" void kernel_launch(void* const* d_in, const int* in_sizes, int n_in,
                              void* d_out, int out_size)
{
  const int*   context = (const int*)  d_in[0];
  const int*   query   = (const int*)  d_in[1];
  const float* E       = (const float*)d_in[2];
  const float* ctx_Wih = (const float*)d_in[3];
  const float* ctx_Whh = (const float*)d_in[4];
  const float* ctx_bih = (const float*)d_in[5];
  const float* ctx_bhh = (const float*)d_in[6];
  const float* q_Wih   = (const float*)d_in[7];
  const float* q_Whh   = (const float*)d_in[8];
  const float* q_bih   = (const float*)d_in[9];
  const float* q_bhh   = (const float*)d_in[10];
  const float* Wq      = (const float*)d_in[11];
  const float* Wp      = (const float*)d_in[12];
  const float* Wr      = (const float*)d_in[13];
  const float* wv      = (const float*)d_in[14];
  const float* gate_b  = (const float*)d_in[15];
  // d_in[16] = attn_bias (softmax-invariant, unused)
  const float* m_Wih   = (const float*)d_in[17];
  const float* m_Whh   = (const float*)d_in[18];
  const float* m_bih   = (const float*)d_in[19];
  const float* m_bhh   = (const float*)d_in[20];
  const float* mr_Wih  = (const float*)d_in[21];
  const float* mr_Whh  = (const float*)d_in[22];
  const float* mr_bih  = (const float*)d_in[23];
  const float* mr_bhh  = (const float*)d_in[24];
  const float* ptr_W1  = (const float*)d_in[25];
  const float* ptr_W2  = (const float*)d_in[26];
  const float* ptr_v   = (const float*)d_in[27];
  const float* d_Wih   = (const float*)d_in[28];
  const float* d_Whh   = (const float*)d_in[29];
  const float* d_bih   = (const float*)d_in[30];
  const float* d_bhh   = (const float*)d_in[31];
  float* out = (float*)d_out;

  float* gictx = (float*)sym(g_gictx);
  float* giq   = (float*)sym(g_giq);
  float* Hp    = (float*)sym(g_Hp);
  float* Hq    = (float*)sym(g_Hq);
  float* whq   = (float*)sym(g_whq);
  float* preWp = (float*)sym(g_preWp);
  float* gixf  = (float*)sym(g_gixf);
  float* gixb  = (float*)sym(g_gixb);
  float* qpf   = (float*)sym(g_qpf);
  float* qpb   = (float*)sym(g_qpb);
  float* Hr    = (float*)sym(g_Hr);
  float* enc   = (float*)sym(g_enc);
  __nv_bfloat16* packs = (__nv_bfloat16*)sym(g_packsb);
  __nv_bfloat16* P_ctx = packs + 0*PACKB_ELEMS;
  __nv_bfloat16* P_q   = packs + 1*PACKB_ELEMS;
  __nv_bfloat16* packm = (__nv_bfloat16*)sym(g_packm);
  __nv_bfloat16* Pm_f  = packm + 0*PACKM_ELEMS;
  __nv_bfloat16* Pm_b  = packm + 1*PACKM_ELEMS;

  // launch 1: prep (embedding GEMMs + all weight packs)
  {
    GDesc dc = {E, context, ctx_Wih, ctx_bih, gictx, Bc*Tc, H3c, Hc, 150, 150, 1, 1, 8, 100};
    GDesc dq = {E, query,   q_Wih,   q_bih,   giq,   Bc*Jc, H3c, Hc, 150, 150, 1, 1, 8, 8};
    prep_kernel<<<dim3(8,100,6),256>>>(dc, dq, ctx_Whh, q_Whh, m_Whh, mr_Whh, Wr,
                                       P_ctx, P_q, Pm_f, Pm_b);
  }

  // launch 2: encoder GRU scans (single CTA per chain)
  cudaFuncSetAttribute(gru_scan_kernel, cudaFuncAttributeMaxDynamicSharedMemorySize, GRU_SMEM);
  gru_scan_kernel<<<64, 480, GRU_SMEM>>>(
      gictx, giq, (const uint4*)P_ctx, (const uint4*)P_q, ctx_bhh, q_bhh, Hp, Hq);

  // launch 3: all six mid GEMMs in one launch
  {
    G6 g;
    g.d[0] = {Hq, nullptr, Wq,          nullptr, whq,   Bc*Jc, Hc,  Hc, Hc, Hc,   0, 0, 3, 8};
    g.d[1] = {Hp, nullptr, Wp,          gate_b,  preWp, Bc*Tc, Hc,  Hc, Hc, Hc,   0, 0, 3, 100};
    g.d[2] = {Hp, nullptr, m_Wih,       m_bih,   gixf,  Bc*Tc, H3c, Hc, Hc, 2*Hc, 1, 0, 8, 100};
    g.d[3] = {Hp, nullptr, mr_Wih,      mr_bih,  gixb,  Bc*Tc, H3c, Hc, Hc, 2*Hc, 1, 0, 8, 100};
    g.d[4] = {Hq, nullptr, m_Wih  + Hc, nullptr, qpf,   Bc*Jc, H3c, Hc, Hc, 2*Hc, 1, 0, 8, 8};
    g.d[5] = {Hq, nullptr, mr_Wih + Hc, nullptr, qpb,   Bc*Jc, H3c, Hc, Hc, 2*Hc, 1, 0, 8, 8};
    multigemm6_kernel<<<dim3(8,100,6),256>>>(g);
  }

  // launch 4: match scans, k-split attention cluster (PROFILE TARGET)
  cudaFuncSetAttribute(match_kernel, cudaFuncAttributeMaxDynamicSharedMemorySize, MATCH_DSMEM);
  match_kernel<<<128, MATCH_THREADS, MATCH_DSMEM>>>(
      whq, preWp, gixf, gixb, qpf, qpb, wv,
      (const uint4*)Pm_f, (const uint4*)Pm_b, m_bhh, mr_bhh, Hr);

  // launch 5: pointer encoder projection
  gemm_kernel<false,false><<<dim3(5,101),256>>>(Hr, nullptr, ptr_W1, nullptr, enc, Bc*TP1c, H2c, H2c, H2c, H2c);

  // launch 6: pointer decoder
  ptr_kernel<<<32,512>>>(Hr, enc, ptr_W2, ptr_v, d_Wih, d_Whh, d_bih, d_bhh, out);
}

// round 16
// speedup vs baseline: 1.1168x; 1.1168x over previous
#include <cuda_runtime.h>
#include <cuda_bf16.h>
#include <cstdint>

#define Bc   32
#define Tc   400
#define Jc   30
#define Hc   150
#define H2c  300
#define H3c  450
#define TP1c 401
#define K8c  19                  // ceil(152/8) k-chunks of 8 (k padded to 152)
#define PACKB_ELEMS (K8c*H3c*8)  // 68400 bf16 per packed gru weight
#define MRc  608                 // match combined rows: 450 Whh + 150 WrT + 8 pad
#define PACKM_ELEMS (K8c*MRc*8)  // 92416 bf16 per packed match weight

typedef unsigned long long ull;

// ---------------- device scratch ----------------
__device__ float g_gictx[Bc*Tc*H3c];
__device__ float g_giq  [Bc*Jc*H3c];
__device__ float g_Hp   [Bc*Tc*Hc];
__device__ float g_Hq   [Bc*Jc*Hc];
__device__ float g_whq  [Bc*Jc*Hc];
__device__ float g_preWp[Bc*Tc*Hc];
__device__ float g_gixf [Bc*Tc*H3c];
__device__ float g_gixb [Bc*Tc*H3c];
__device__ float g_qpf  [Bc*Jc*H3c];
__device__ float g_qpb  [Bc*Jc*H3c];
__device__ float g_Hr   [Bc*TP1c*H2c];
__device__ float g_enc  [Bc*TP1c*H2c];
__device__ __align__(16) __nv_bfloat16 g_packsb[2*PACKB_ELEMS];
__device__ __align__(16) __nv_bfloat16 g_packm [2*PACKM_ELEMS];

// ---------------- fast activations ----------------
__device__ __forceinline__ float fast_ex2(float x){ float y; asm("ex2.approx.f32 %0, %1;" : "=f"(y) : "f"(x)); return y; }
__device__ __forceinline__ float tanh_f(float x){ float y; asm("tanh.approx.f32 %0, %1;" : "=f"(y) : "f"(x)); return y; }
__device__ __forceinline__ float sigm(float x){ return fmaf(tanh_f(0.5f*x), 0.5f, 0.5f); }

// ---------------- f32x2 packed math ----------------
__device__ __forceinline__ void ffma2(ull &acc, ull a, ull b){
  asm("fma.rn.f32x2 %0, %1, %2, %0;" : "+l"(acc) : "l"(a), "l"(b));
}
__device__ __forceinline__ ull packf2(float x){
  ull r; asm("mov.b64 %0, {%1, %1};" : "=l"(r) : "f"(x)); return r;
}
__device__ __forceinline__ ull pack2(float x, float y){
  ull r; asm("mov.b64 %0, {%1, %2};" : "=l"(r) : "f"(x), "f"(y)); return r;
}
__device__ __forceinline__ float2 unpackf2(ull v){
  float lo, hi; asm("mov.b64 {%0, %1}, %2;" : "=f"(lo), "=f"(hi) : "l"(v));
  return make_float2(lo, hi);
}
// EXACT bf16x2 -> f32x2: bf16 is truncated fp32 (lo: <<16, hi: mask)
__device__ __forceinline__ ull bf2f2(uint32_t w){
  uint32_t lo = w << 16;
  uint32_t hi = w & 0xFFFF0000u;
  ull r; asm("mov.b64 %0, {%1, %2};" : "=l"(r) : "r"(lo), "r"(hi)); return r;
}
// 8 MACs: w = 8 bf16 (k..k+7), h0/h1 = matching fp32 values; two f32x2 accumulators
__device__ __forceinline__ void fma8v2(uint4 w, float4 h0, float4 h1, ull &accA, ull &accB){
  ffma2(accA, bf2f2(w.x), pack2(h0.x, h0.y));
  ffma2(accB, bf2f2(w.y), pack2(h0.z, h0.w));
  ffma2(accA, bf2f2(w.z), pack2(h1.x, h1.y));
  ffma2(accB, bf2f2(w.w), pack2(h1.z, h1.w));
}
__device__ __forceinline__ float finish2(ull accA, ull accB, float init){
  float2 a = unpackf2(accA), b = unpackf2(accB);
  return init + ((a.x + a.y) + (b.x + b.y));
}
__device__ __forceinline__ float4 ld4(const float* p){ return *reinterpret_cast<const float4*>(p); }

// ---------------- cluster / mbarrier / cp.async helpers ----------------
__device__ __forceinline__ uint32_t smem_u32(const void* p){
  uint32_t a; asm("{ .reg .u64 t; cvta.to.shared.u64 t, %1; cvt.u32.u64 %0, t; }" : "=r"(a) : "l"(p));
  return a;
}
__device__ __forceinline__ uint32_t mapa_u32(uint32_t a, uint32_t rank){
  uint32_t r; asm("mapa.shared::cluster.u32 %0, %1, %2;" : "=r"(r) : "r"(a), "r"(rank));
  return r;
}
__device__ __forceinline__ void mbar_init(uint32_t a, uint32_t cnt){
  asm volatile("mbarrier.init.shared.b64 [%0], %1;" :: "r"(a), "r"(cnt) : "memory");
}
__device__ __forceinline__ void mbar_arrive_cluster(uint32_t remote){
  asm volatile("mbarrier.arrive.release.cluster.shared::cluster.b64 _, [%0];" :: "r"(remote) : "memory");
}
__device__ __forceinline__ void mbar_wait(uint32_t a, uint32_t parity){
  uint32_t done;
  asm volatile("{\n\t.reg .pred p;\n\t"
    "mbarrier.try_wait.parity.acquire.cluster.shared::cta.b64 p, [%1], %2;\n\t"
    "selp.b32 %0, 1, 0, p;\n\t}" : "=r"(done) : "r"(a), "r"(parity) : "memory");
  while (!done) {
    asm volatile("{\n\t.reg .pred p;\n\t"
      "mbarrier.try_wait.parity.acquire.cluster.shared::cta.b64 p, [%1], %2, 0x989680;\n\t"
      "selp.b32 %0, 1, 0, p;\n\t}" : "=r"(done) : "r"(a), "r"(parity) : "memory");
  }
}
__device__ __forceinline__ void sts_remote_f32(uint32_t a, float v){
  asm volatile("st.shared::cluster.f32 [%0], %1;" :: "r"(a), "f"(v) : "memory");
}
__device__ __forceinline__ void cp_async4(uint32_t saddr, const void* gptr, bool ok){
  int sz = ok ? 4 : 0;
  asm volatile("cp.async.ca.shared.global [%0], [%1], 4, %2;"
               :: "r"(saddr), "l"(gptr), "r"(sz) : "memory");
}
#define CP_COMMIT() asm volatile("cp.async.commit_group;" ::: "memory")
#define CLUSTER_SYNC_() do{ \
  asm volatile("barrier.cluster.arrive.aligned;" ::: "memory"); \
  asm volatile("barrier.cluster.wait.aligned;" ::: "memory"); } while(0)

// ---------------- shared GEMM body: cp.async 3-stage pipelined, FFMA2 compute ----------------
__device__ __forceinline__ void gemm_body(
    const float* __restrict__ A, const int* __restrict__ idx,
    const float* __restrict__ W, const float* __restrict__ bias,
    float* __restrict__ C, int M, int N, int K, int lda, int ldw,
    bool transw, bool gather)
{
  __shared__ __align__(16) float As[3][16][132];
  __shared__ __align__(16) float Bs[3][16][68];
  __shared__ int sidx[128];
  int m0 = blockIdx.y*128, n0 = blockIdx.x*64;
  int tid = threadIdx.x;
  int tx = tid & 15, ty = tid >> 4;
  ull acc2[8][2] = {};
  int nk = (K + 15) >> 4;

  if (gather) {
    for (int i = tid; i < 128; i += 256) {
      int gm = m0 + i;
      sidx[i] = (gm < M) ? idx[gm] : 0;
    }
    __syncthreads();
  }
  uint32_t asb = smem_u32(&As[0][0][0]);
  uint32_t bsb = smem_u32(&Bs[0][0][0]);

  auto issue_tile = [&](int itile){
    int bo = itile % 3;
    int k0 = itile*16;
    uint32_t abase = asb + (uint32_t)bo*16*132*4;
    uint32_t bbase = bsb + (uint32_t)bo*16*68*4;
    #pragma unroll
    for (int it = 0; it < 8; it++) {
      int li = tid + it*256;
      int m = li >> 4, k = li & 15;
      int gm = m0 + m, gk = k0 + k;
      bool ok = (gm < M) && (gk < K);
      int row = gather ? sidx[m] : gm;
      const float* src = A + (size_t)(ok ? row : 0)*lda + (ok ? gk : 0);
      cp_async4(abase + (uint32_t)(k*132 + m)*4, src, ok);
    }
    #pragma unroll
    for (int it = 0; it < 4; it++) {
      int li = tid + it*256;
      if (transw) {
        int n = li >> 4, k = li & 15;
        int gn = n0 + n, gk = k0 + k;
        bool ok = (gn < N) && (gk < K);
        const float* src = W + (size_t)(ok ? gn : 0)*ldw + (ok ? gk : 0);
        cp_async4(bbase + (uint32_t)(k*68 + n)*4, src, ok);
      } else {
        int k = li >> 6, n = li & 63;
        int gn = n0 + n, gk = k0 + k;
        bool ok = (gn < N) && (gk < K);
        const float* src = W + (size_t)(ok ? gk : 0)*ldw + (ok ? gn : 0);
        cp_async4(bbase + (uint32_t)(k*68 + n)*4, src, ok);
      }
    }
    CP_COMMIT();
  };

  issue_tile(0);
  if (nk > 1) issue_tile(1);
  for (int itile = 0; itile < nk; itile++) {
    if (itile + 2 < nk) {
      issue_tile(itile + 2);
      asm volatile("cp.async.wait_group 2;" ::: "memory");
    } else if (itile + 1 < nk) {
      asm volatile("cp.async.wait_group 1;" ::: "memory");
    } else {
      asm volatile("cp.async.wait_group 0;" ::: "memory");
    }
    __syncthreads();
    int cb = itile % 3;
    #pragma unroll
    for (int k = 0; k < 16; k++) {
      const ull* bv2 = reinterpret_cast<const ull*>(&Bs[cb][k][tx*4]);
      ull b01 = bv2[0], b23 = bv2[1];
      float4 a0 = *reinterpret_cast<const float4*>(&As[cb][k][ty*8]);
      float4 a1 = *reinterpret_cast<const float4*>(&As[cb][k][ty*8+4]);
      float am[8] = {a0.x,a0.y,a0.z,a0.w,a1.x,a1.y,a1.z,a1.w};
      #pragma unroll
      for (int i = 0; i < 8; i++) {
        ull am2 = packf2(am[i]);
        ffma2(acc2[i][0], am2, b01);
        ffma2(acc2[i][1], am2, b23);
      }
    }
    __syncthreads();
  }

  #pragma unroll
  for (int i = 0; i < 8; i++) {
    int gm = m0 + ty*8 + i;
    if (gm >= M) continue;
    float2 p0 = unpackf2(acc2[i][0]);
    float2 p1 = unpackf2(acc2[i][1]);
    float vals[4] = {p0.x, p0.y, p1.x, p1.y};
    #pragma unroll
    for (int j = 0; j < 4; j++) {
      int gn = n0 + tx*4 + j;
      if (gn < N) {
        float v = vals[j];
        if (bias) v += bias[gn];
        C[(size_t)gm*N + gn] = v;
      }
    }
  }
}

template<bool TRANSW, bool GATHER>
__global__ void __launch_bounds__(256) gemm_kernel(
    const float* __restrict__ A, const int* __restrict__ idx,
    const float* __restrict__ W, const float* __restrict__ bias,
    float* __restrict__ C, int M, int N, int K, int lda, int ldw)
{
  gemm_body(A, idx, W, bias, C, M, N, K, lda, ldw, TRANSW, GATHER);
}

struct GDesc {
  const float* A; const int* idx; const float* W; const float* bias; float* C;
  int M, N, K, lda, ldw, transw, gather, gx, gy;
};
struct G6 { GDesc d[6]; };

__global__ void __launch_bounds__(256) multigemm6_kernel(G6 g)
{
  GDesc d = g.d[blockIdx.z];
  if ((int)blockIdx.x >= d.gx || (int)blockIdx.y >= d.gy) return;
  gemm_body(d.A, d.idx, d.W, d.bias, d.C, d.M, d.N, d.K, d.lda, d.ldw,
            d.transw != 0, d.gather != 0);
}

// ---------------- prep: z0/z1 = embedding GEMMs, z2..5 = weight packs ----------------
__global__ void __launch_bounds__(256) prep_kernel(
    GDesc d0, GDesc d1,
    const float* __restrict__ ctx_Whh, const float* __restrict__ q_Whh,
    const float* __restrict__ m_Whh,  const float* __restrict__ mr_Whh,
    const float* __restrict__ Wr,
    __nv_bfloat16* __restrict__ P_ctx, __nv_bfloat16* __restrict__ P_q,
    __nv_bfloat16* __restrict__ Pm_f,  __nv_bfloat16* __restrict__ Pm_b)
{
  int z = blockIdx.z;
  if (z < 2) {
    GDesc d = z ? d1 : d0;
    if ((int)blockIdx.x >= d.gx || (int)blockIdx.y >= d.gy) return;
    gemm_body(d.A, d.idx, d.W, d.bias, d.C, d.M, d.N, d.K, d.lda, d.ldw,
              d.transw != 0, d.gather != 0);
    return;
  }
  int i = (blockIdx.y*8 + blockIdx.x)*256 + threadIdx.x;
  if (z < 4) {
    if (i >= PACKB_ELEMS) return;
    const float* W = (z == 3) ? q_Whh : ctx_Whh;
    __nv_bfloat16* out = (z == 3) ? P_q : P_ctx;
    int kk = i & 7, rest = i >> 3;
    int n = rest % H3c, k8 = rest / H3c, k = k8*8 + kk;
    out[i] = __float2bfloat16((k < Hc) ? W[n*Hc + k] : 0.f);
  } else {
    if (i >= PACKM_ELEMS) return;
    const float* Whh = (z == 4) ? m_Whh : mr_Whh;
    __nv_bfloat16* out = (z == 4) ? Pm_f : Pm_b;
    int kk = i & 7, rest = i >> 3;
    int row = rest % MRc, k8 = rest / MRc, k = k8*8 + kk;
    float v = 0.f;
    if (k < Hc) {
      if (row < H3c)      v = Whh[row*Hc + k];
      else if (row < 600) v = Wr[k*Hc + (row - H3c)];
    }
    out[i] = __float2bfloat16(v);
  }
}

// ---------------- GRU scans: single CTA per chain, shift-trick FFMA2 inner loop ----------------
#define GRU_SMEM (K8c*H3c*16)   // 136800 B

__global__ void __launch_bounds__(480,1) gru_scan_kernel(
    const float* __restrict__ gictx, const float* __restrict__ giq,
    const uint4* __restrict__ PctxWhh, const uint4* __restrict__ PqWhh,
    const float* __restrict__ ctx_bhh, const float* __restrict__ q_bhh,
    float* __restrict__ Hp, float* __restrict__ Hq)
{
  extern __shared__ uint4 sW4g[];  // [k8*450 + n]
  __shared__ float sh[152];
  __shared__ float sgh[452];
  int tid = threadIdx.x;
  int isq = blockIdx.x >> 5;
  int b   = blockIdx.x & 31;
  const float* gi   = isq ? (giq + (size_t)b*Jc*H3c) : (gictx + (size_t)b*Tc*H3c);
  const uint4* Wsrc = isq ? PqWhh : PctxWhh;
  const float* bhh  = isq ? q_bhh : ctx_bhh;
  float*       outp = isq ? (Hq + (size_t)b*Jc*Hc) : (Hp + (size_t)b*Tc*Hc);
  int Tlen = isq ? Jc : Tc;

  for (int i = tid; i < K8c*H3c; i += 480) sW4g[i] = Wsrc[i];
  float my_b = (tid < H3c) ? bhh[tid] : 0.f;
  if (tid < 152) sh[tid] = 0.f;
  __syncthreads();

  for (int t = 0; t < Tlen; t++) {
    float gi0=0.f, gi1=0.f, gi2=0.f;
    if (tid < Hc) {
      const float* gr = gi + (size_t)t*H3c;
      gi0 = gr[tid]; gi1 = gr[Hc+tid]; gi2 = gr[2*Hc+tid];
    }
    if (tid < H3c) {
      ull accA = 0ull, accB = 0ull;
      const uint4* wr = sW4g + tid;
      #pragma unroll
      for (int k8 = 0; k8 < K8c; k8++) {
        uint4 w = wr[k8*H3c];
        fma8v2(w, ld4(sh + k8*8), ld4(sh + k8*8 + 4), accA, accB);
      }
      sgh[tid] = finish2(accA, accB, my_b);
    }
    __syncthreads();
    if (tid < Hc) {
      float r  = sigm(gi0 + sgh[tid]);
      float z  = sigm(gi1 + sgh[Hc + tid]);
      float nn = tanh_f(gi2 + r*sgh[2*Hc + tid]);
      float hn = nn + z*(sh[tid] - nn);
      sh[tid] = hn;
      outp[(size_t)t*Hc + tid] = hn;
    }
    __syncthreads();
  }
}

// ---------------- match scans: rank-specialized 2-CTA cluster, ONE exchange/step ----------------
// rank0: gh rows 0..383.  rank1: gh rows 384..449 + e rows 450..599 + attention + softmax.
#define MATCH_THREADS 512
#define R0_ROWS 384
#define R1_ROWS 216
#define MATCH_WSMEM (K8c*R0_ROWS*16)                       // 116736 B (max of both ranks)
#define MATCH_DSMEM (MATCH_WSMEM + 450*32*2 + Jc*152*2)    // +28800+9120 = 154656 B

__global__ void __launch_bounds__(MATCH_THREADS,1) __cluster_dims__(2,1,1)
match_kernel(
    const float* __restrict__ whq,  const float* __restrict__ preWp,
    const float* __restrict__ gixf, const float* __restrict__ gixb,
    const float* __restrict__ qpf,  const float* __restrict__ qpb,
    const float* __restrict__ wvec,
    const uint4* __restrict__ WcPf, const uint4* __restrict__ WcPb,
    const float* __restrict__ m_bhh, const float* __restrict__ mr_bhh,
    float* __restrict__ Hr)
{
  extern __shared__ uint4 sWm[];                            // rank0:[19][384] rank1:[19][216]
  __nv_bfloat16* sQPT = (__nv_bfloat16*)((char*)sWm + MATCH_WSMEM); // [450][32]
  __nv_bfloat16* sWhq = sQPT + 450*32;                      // [30][152]
  __shared__ float sh [152];
  __shared__ float sw [152];
  __shared__ float se [152];          // e rows (rank1 local only)
  __shared__ float sS [32];           // raw attention scores (rank1 local)
  __shared__ float sghe[2][456];      // double-buffered full gh (450)
  __shared__ float sAb [2][32];       // double-buffered softmax result
  __shared__ __align__(8) unsigned long long mbar_in;

  int tid = threadIdx.x;
  uint32_t rank; asm("mov.u32 %0, %%cluster_ctarank;" : "=r"(rank));
  int chain = blockIdx.x >> 1;      // 0..63
  int dir = chain >> 5;
  int b   = chain & 31;

  const float* gix = (dir ? gixb : gixf) + (size_t)b*Tc*H3c;
  const float* qp  = (dir ? qpb  : qpf)  + (size_t)b*Jc*H3c;
  const uint4* Wc  = dir ? WcPb : WcPf;
  const float* bhh = dir ? mr_bhh : m_bhh;
  const float* preW = preWp + (size_t)b*Tc*Hc;

  int R = rank ? R1_ROWS : R0_ROWS;          // my row count
  int rbase = rank ? R0_ROWS : 0;            // my first global row

  // preamble: weights (my rows), qproj^T, whq
  for (int i = tid; i < K8c*R; i += MATCH_THREADS) {
    int k8 = i / R, rl = i % R;
    sWm[i] = Wc[k8*MRc + rbase + rl];
  }
  for (int i = tid; i < Jc*H3c; i += MATCH_THREADS) {
    int j = i / H3c, n = i % H3c;
    sQPT[n*32 + j] = __float2bfloat16(qp[i]);
  }
  for (int n = tid; n < H3c; n += MATCH_THREADS) {
    sQPT[n*32 + 30] = __float2bfloat16(0.f);
    sQPT[n*32 + 31] = __float2bfloat16(0.f);
  }
  for (int i = tid; i < Jc*Hc; i += MATCH_THREADS) {
    int j = i / Hc, k = i % Hc;
    sWhq[j*152 + k] = __float2bfloat16(whq[(size_t)b*Jc*Hc + i]);
  }
  if (tid < 152) { sw[tid] = (tid < Hc) ? wvec[tid] : 0.f; sh[tid] = 0.f; }
  if (rank == 0 && tid < Hc) Hr[((size_t)b*TP1c)*H2c + dir*Hc + tid] = 0.f;
  int grow = rbase + tid;                   // my global row index (if tid < R)
  float my_bhh = (tid < R && grow < H3c) ? bhh[grow] : 0.f;
  if (tid == 0) mbar_init(smem_u32(&mbar_in), 1);
  __syncthreads();
  CLUSTER_SYNC_();
  uint32_t peer_sghe = mapa_u32(smem_u32(&sghe[0][0]), rank ^ 1);
  uint32_t peer_sAb  = mapa_u32(smem_u32(&sAb[0][0]),  rank ^ 1);
  uint32_t peer_mbar = mapa_u32(smem_u32(&mbar_in), rank ^ 1);
  uint32_t my_mbar   = smem_u32(&mbar_in);

  for (int step = 0; step < Tc; step++) {
    int t = dir ? (Tc-1-step) : step;
    int buf = step & 1;

    // prefetch per-step gate inputs (consumed in S4) + preW for e-rows (rank1)
    float g0=0.f, g1=0.f, g2=0.f;
    if (tid < Hc) {
      const float* gr = gix + (size_t)t*H3c;
      g0 = gr[tid]; g1 = gr[Hc+tid]; g2 = gr[2*Hc+tid];
    }
    float pw = 0.f;
    if (rank && tid < R && grow >= 600-Hc) pw = preW[(size_t)t*Hc + (grow - H3c)];

    // S1: my rows of the combined matvec
    if (tid < R) {
      float init = (grow < H3c) ? my_bhh : pw;
      ull accA = 0ull, accB = 0ull;
      #pragma unroll
      for (int k8 = 0; k8 < K8c; k8++) {
        uint4 w = sWm[k8*R + tid];
        fma8v2(w, ld4(sh + k8*8), ld4(sh + k8*8 + 4), accA, accB);
      }
      float acc = finish2(accA, accB, init);
      if (grow < H3c) {
        sghe[buf][grow] = acc;
        sts_remote_f32(peer_sghe + (uint32_t)(buf*456 + grow)*4u, acc);
      } else {
        se[grow - H3c] = acc;      // rank1 local e
      }
    }
    __syncthreads();

    if (rank == 0) {
      // send gh[0:384], then wait for rank1's gh[384:450] + sA
      if (tid == 0) mbar_arrive_cluster(peer_mbar);
      mbar_wait(my_mbar, (uint32_t)buf);
    } else {
      // S2: attention scores (16 warps, 2 j each, local e)
      {
        int wid = tid >> 5, lane = tid & 31;
        #pragma unroll
        for (int jj = 0; jj < 2; jj++) {
          int j = wid*2 + jj;
          if (j < Jc) {
            float p = 0.f;
            for (int k = lane; k < Hc; k += 32)
              p = fmaf(tanh_f(__bfloat162float(sWhq[j*152 + k]) + se[k]), sw[k], p);
            #pragma unroll
            for (int o = 16; o; o >>= 1) p += __shfl_xor_sync(0xffffffffu, p, o);
            if (lane == 0) sS[j] = p;
          }
        }
      }
      __syncthreads();
      // S3: softmax (warp 0), write local + remote
      if (tid < 32) {
        float v = (tid < Jc) ? sS[tid] : -1e30f;
        float m = v;
        #pragma unroll
        for (int o = 16; o; o >>= 1) m = fmaxf(m, __shfl_xor_sync(0xffffffffu, m, o));
        float e = (tid < Jc) ? fast_ex2(1.442695041f*(v - m)) : 0.f;
        float su = e;
        #pragma unroll
        for (int o = 16; o; o >>= 1) su += __shfl_xor_sync(0xffffffffu, su, o);
        float a = e * __fdividef(1.f, su);
        sAb[buf][tid] = a;
        sts_remote_f32(peer_sAb + (uint32_t)(buf*32 + tid)*4u, a);
      }
      __syncthreads();
      if (tid == 0) mbar_arrive_cluster(peer_mbar);
      mbar_wait(my_mbar, (uint32_t)buf);   // rank0's gh[0:384]
    }

    // S4: gates + GRU update (replicated, bitwise identical); Hr store on rank0
    if (tid < Hc) {
      ull aR = 0ull, bR = 0ull, aZ = 0ull, bZ = 0ull, aN = 0ull, bN = 0ull;
      const uint4* qr = reinterpret_cast<const uint4*>(sQPT + tid*32);
      const uint4* qz = reinterpret_cast<const uint4*>(sQPT + (Hc + tid)*32);
      const uint4* qn = reinterpret_cast<const uint4*>(sQPT + (2*Hc + tid)*32);
      #pragma unroll
      for (int jj = 0; jj < 4; jj++) {
        float4 a0 = ld4(&sAb[buf][jj*8]);
        float4 a1 = ld4(&sAb[buf][jj*8 + 4]);
        fma8v2(qr[jj], a0, a1, aR, bR);
        fma8v2(qz[jj], a0, a1, aZ, bZ);
        fma8v2(qn[jj], a0, a1, aN, bN);
      }
      float gr_ = finish2(aR, bR, g0);
      float gz_ = finish2(aZ, bZ, g1);
      float gn_ = finish2(aN, bN, g2);
      float r  = sigm(gr_ + sghe[buf][tid]);
      float z  = sigm(gz_ + sghe[buf][Hc+tid]);
      float nn = tanh_f(gn_ + r*sghe[buf][2*Hc+tid]);
      float hn = nn + z*(sh[tid] - nn);
      sh[tid] = hn;
      if (rank == 0) Hr[((size_t)b*TP1c + 1 + step)*H2c + dir*Hc + tid] = hn;
    }
    __syncthreads();
  }
  CLUSTER_SYNC_();
}

// ---------------- pointer decoder (32 blocks, 2 steps), vectorized GEMVs ----------------
__global__ void __launch_bounds__(512,1) ptr_kernel(
    const float* __restrict__ Hr, const float* __restrict__ enc,
    const float* __restrict__ ptr_W2, const float* __restrict__ ptr_v,
    const float* __restrict__ d_Wih, const float* __restrict__ d_Whh,
    const float* __restrict__ d_bih, const float* __restrict__ d_bhh,
    float* __restrict__ out)
{
  __shared__ __align__(16) float sh[H2c], shw[H2c], sc[H2c];
  __shared__ float sa[TP1c + 3], sgi[900], sgh[900];
  __shared__ float red[2];
  int b = blockIdx.x, tid = threadIdx.x;
  int wid = tid >> 5, lane = tid & 31;
  const float* encb = enc + (size_t)b*TP1c*H2c;
  const float* Hrb  = Hr  + (size_t)b*TP1c*H2c;
  if (tid < H2c) sh[tid] = 0.f;
  __syncthreads();

  for (int step = 0; step < 2; step++) {
    // hw2 = h @ ptr_W2 (dual accumulators for MLP)
    if (tid < H2c) {
      float a0 = 0.f, a1 = 0.f;
      for (int j = 0; j < H2c; j += 2) {
        a0 = fmaf(sh[j],   ptr_W2[(size_t)j*H2c + tid],       a0);
        a1 = fmaf(sh[j+1], ptr_W2[(size_t)(j+1)*H2c + tid],   a1);
      }
      shw[tid] = a0 + a1;
    }
    __syncthreads();
    // scores over T+1 positions
    for (int t = wid; t < TP1c; t += 16) {
      float p = 0.f;
      const float* er = encb + (size_t)t*H2c;
      for (int k = lane; k < H2c; k += 32) p = fmaf(tanh_f(er[k] + shw[k]), ptr_v[k], p);
      #pragma unroll
      for (int o = 16; o; o >>= 1) p += __shfl_xor_sync(0xffffffffu, p, o);
      if (lane == 0) sa[t] = p;
    }
    __syncthreads();
    if (tid < 32) {
      float m = -1e30f;
      for (int t = lane; t < TP1c; t += 32) m = fmaxf(m, sa[t]);
      #pragma unroll
      for (int o = 16; o; o >>= 1) m = fmaxf(m, __shfl_xor_sync(0xffffffffu, m, o));
      if (lane == 0) red[0] = m;
    }
    __syncthreads();
    float mm = red[0];
    for (int t = tid; t < TP1c; t += 512) sa[t] = fast_ex2(1.442695041f*(sa[t] - mm));
    __syncthreads();
    if (tid < 32) {
      float s = 0.f;
      for (int t = lane; t < TP1c; t += 32) s += sa[t];
      #pragma unroll
      for (int o = 16; o; o >>= 1) s += __shfl_xor_sync(0xffffffffu, s, o);
      if (lane == 0) red[1] = __fdividef(1.f, s);
    }
    __syncthreads();
    float inv = red[1];
    for (int t = tid; t < TP1c; t += 512) {
      float a = sa[t] * inv;
      sa[t] = a;
      out[((size_t)b*2 + step)*TP1c + t] = a;
    }
    __syncthreads();
    // c = a @ Hr  (4 independent accumulators for MLP)
    if (tid < H2c) {
      float a0 = 0.f, a1 = 0.f, a2 = 0.f, a3 = 0.f;
      int t = 0;
      for (; t + 4 <= TP1c; t += 4) {
        a0 = fmaf(sa[t],   Hrb[(size_t)t*H2c + tid],       a0);
        a1 = fmaf(sa[t+1], Hrb[(size_t)(t+1)*H2c + tid],   a1);
        a2 = fmaf(sa[t+2], Hrb[(size_t)(t+2)*H2c + tid],   a2);
        a3 = fmaf(sa[t+3], Hrb[(size_t)(t+3)*H2c + tid],   a3);
      }
      for (; t < TP1c; t++) a0 = fmaf(sa[t], Hrb[(size_t)t*H2c + tid], a0);
      sc[tid] = (a0 + a1) + (a2 + a3);
    }
    __syncthreads();
    // decoder GRU (hidden 300, gates 900): float4 rows, dual accumulators
    for (int n = tid; n < 900; n += 512) {
      const float4* wi = reinterpret_cast<const float4*>(d_Wih + (size_t)n*H2c);
      const float4* wh = reinterpret_cast<const float4*>(d_Whh + (size_t)n*H2c);
      float giA = d_bih[n], giB = 0.f, ghA = d_bhh[n], ghB = 0.f;
      #pragma unroll 5
      for (int q = 0; q < H2c/4; q++) {
        float4 w1 = wi[q], w2 = wh[q];
        float4 c4 = ld4(sc + q*4);
        float4 h4 = ld4(sh + q*4);
        giA = fmaf(c4.x, w1.x, giA); giB = fmaf(c4.y, w1.y, giB);
        giA = fmaf(c4.z, w1.z, giA); giB = fmaf(c4.w, w1.w, giB);
        ghA = fmaf(h4.x, w2.x, ghA); ghB = fmaf(h4.y, w2.y, ghB);
        ghA = fmaf(h4.z, w2.z, ghA); ghB = fmaf(h4.w, w2.w, ghB);
      }
      sgi[n] = giA + giB; sgh[n] = ghA + ghB;
    }
    __syncthreads();
    if (tid < H2c) {
      float r  = sigm(sgi[tid] + sgh[tid]);
      float z  = sigm(sgi[H2c+tid] + sgh[H2c+tid]);
      float nn = tanh_f(sgi[2*H2c+tid] + r*sgh[2*H2c+tid]);
      sh[tid] = nn + z*(sh[tid] - nn);
    }
    __syncthreads();
  }
}

// ---------------- host ----------------
static void* sym(const void* s) { void* p = nullptr; cudaGetSymbolAddress(&p, s); return p; }

extern "C" void kernel_launch(void* const* d_in, const int* in_sizes, int n_in,
                              void* d_out, int out_size)
{
  const int*   context = (const int*)  d_in[0];
  const int*   query   = (const int*)  d_in[1];
  const float* E       = (const float*)d_in[2];
  const float* ctx_Wih = (const float*)d_in[3];
  const float* ctx_Whh = (const float*)d_in[4];
  const float* ctx_bih = (const float*)d_in[5];
  const float* ctx_bhh = (const float*)d_in[6];
  const float* q_Wih   = (const float*)d_in[7];
  const float* q_Whh   = (const float*)d_in[8];
  const float* q_bih   = (const float*)d_in[9];
  const float* q_bhh   = (const float*)d_in[10];
  const float* Wq      = (const float*)d_in[11];
  const float* Wp      = (const float*)d_in[12];
  const float* Wr      = (const float*)d_in[13];
  const float* wv      = (const float*)d_in[14];
  const float* gate_b  = (const float*)d_in[15];
  // d_in[16] = attn_bias (softmax-invariant, unused)
  const float* m_Wih   = (const float*)d_in[17];
  const float* m_Whh   = (const float*)d_in[18];
  const float* m_bih   = (const float*)d_in[19];
  const float* m_bhh   = (const float*)d_in[20];
  const float* mr_Wih  = (const float*)d_in[21];
  const float* mr_Whh  = (const float*)d_in[22];
  const float* mr_bih  = (const float*)d_in[23];
  const float* mr_bhh  = (const float*)d_in[24];
  const float* ptr_W1  = (const float*)d_in[25];
  const float* ptr_W2  = (const float*)d_in[26];
  const float* ptr_v   = (const float*)d_in[27];
  const float* d_Wih   = (const float*)d_in[28];
  const float* d_Whh   = (const float*)d_in[29];
  const float* d_bih   = (const float*)d_in[30];
  const float* d_bhh   = (const float*)d_in[31];
  float* out = (float*)d_out;

  float* gictx = (float*)sym(g_gictx);
  float* giq   = (float*)sym(g_giq);
  float* Hp    = (float*)sym(g_Hp);
  float* Hq    = (float*)sym(g_Hq);
  float* whq   = (float*)sym(g_whq);
  float* preWp = (float*)sym(g_preWp);
  float* gixf  = (float*)sym(g_gixf);
  float* gixb  = (float*)sym(g_gixb);
  float* qpf   = (float*)sym(g_qpf);
  float* qpb   = (float*)sym(g_qpb);
  float* Hr    = (float*)sym(g_Hr);
  float* enc   = (float*)sym(g_enc);
  __nv_bfloat16* packs = (__nv_bfloat16*)sym(g_packsb);
  __nv_bfloat16* P_ctx = packs + 0*PACKB_ELEMS;
  __nv_bfloat16* P_q   = packs + 1*PACKB_ELEMS;
  __nv_bfloat16* packm = (__nv_bfloat16*)sym(g_packm);
  __nv_bfloat16* Pm_f  = packm + 0*PACKM_ELEMS;
  __nv_bfloat16* Pm_b  = packm + 1*PACKM_ELEMS;

  // launch 1: prep (embedding GEMMs + all weight packs)
  {
    GDesc dc = {E, context, ctx_Wih, ctx_bih, gictx, Bc*Tc, H3c, Hc, 150, 150, 1, 1, 8, 100};
    GDesc dq = {E, query,   q_Wih,   q_bih,   giq,   Bc*Jc, H3c, Hc, 150, 150, 1, 1, 8, 8};
    prep_kernel<<<dim3(8,100,6),256>>>(dc, dq, ctx_Whh, q_Whh, m_Whh, mr_Whh, Wr,
                                       P_ctx, P_q, Pm_f, Pm_b);
  }

  // launch 2: encoder GRU scans (single CTA per chain)
  cudaFuncSetAttribute(gru_scan_kernel, cudaFuncAttributeMaxDynamicSharedMemorySize, GRU_SMEM);
  gru_scan_kernel<<<64, 480, GRU_SMEM>>>(
      gictx, giq, (const uint4*)P_ctx, (const uint4*)P_q, ctx_bhh, q_bhh, Hp, Hq);

  // launch 3: all six mid GEMMs in one launch
  {
    G6 g;
    g.d[0] = {Hq, nullptr, Wq,          nullptr, whq,   Bc*Jc, Hc,  Hc, Hc, Hc,   0, 0, 3, 8};
    g.d[1] = {Hp, nullptr, Wp,          gate_b,  preWp, Bc*Tc, Hc,  Hc, Hc, Hc,   0, 0, 3, 100};
    g.d[2] = {Hp, nullptr, m_Wih,       m_bih,   gixf,  Bc*Tc, H3c, Hc, Hc, 2*Hc, 1, 0, 8, 100};
    g.d[3] = {Hp, nullptr, mr_Wih,      mr_bih,  gixb,  Bc*Tc, H3c, Hc, Hc, 2*Hc, 1, 0, 8, 100};
    g.d[4] = {Hq, nullptr, m_Wih  + Hc, nullptr, qpf,   Bc*Jc, H3c, Hc, Hc, 2*Hc, 1, 0, 8, 8};
    g.d[5] = {Hq, nullptr, mr_Wih + Hc, nullptr, qpb,   Bc*Jc, H3c, Hc, Hc, 2*Hc, 1, 0, 8, 8};
    multigemm6_kernel<<<dim3(8,100,6),256>>>(g);
  }

  // launch 4: match scans, rank-specialized cluster (PROFILE TARGET)
  cudaFuncSetAttribute(match_kernel, cudaFuncAttributeMaxDynamicSharedMemorySize, MATCH_DSMEM);
  match_kernel<<<128, MATCH_THREADS, MATCH_DSMEM>>>(
      whq, preWp, gixf, gixb, qpf, qpb, wv,
      (const uint4*)Pm_f, (const uint4*)Pm_b, m_bhh, mr_bhh, Hr);

  // launch 5: pointer encoder projection
  gemm_kernel<false,false><<<dim3(5,101),256>>>(Hr, nullptr, ptr_W1, nullptr, enc, Bc*TP1c, H2c, H2c, H2c, H2c);

  // launch 6: pointer decoder
  ptr_kernel<<<32,512>>>(Hr, enc, ptr_W2, ptr_v, d_Wih, d_Whh, d_bih, d_bhh, out);
}